// round 11
// baseline (speedup 1.0000x reference)
#include <cuda_runtime.h>
#include <cstdint>

// ============================================================================
// NNLS via normal equations, FFMA2 (f32x2), triangle lane-jobs, UNIFIED
// 48-float-stride buffer (rows 192B => bank period 0 mod 32, constant strides):
//   row = [x0..x31 | y0..y3 | v 0 0 0 | pad(8)]
// Per warp: rows r = w + 8k. 29 lane jobs, one uniform stream
//   (2x LDS.128 a-pairs, 1x LDS.128 b-quad, 4 dup, 16 FFMA2):
//   kind0 (20): G upper-triangle 8x4 tiles
//   kind1 (4) : c tiles      (b = y quad @32)
//   kind2 (4) : colsum tiles (b = v quad @36)
//   kind3 (1) : ysum + count (a = row @32, b = v quad @36)
// Then tiny projected-gradient QP solve (G ~ N*I, kappa ~ 1.02).
// ============================================================================

#define TPB 256
#define NCTA 296
#define PGD_ITERS 48

// ACC: [0..1023] G tiles, [1024..1151] c[i][m], [1152..1183] colsum,
//      [1184..1187] ysum, [1188] count
__device__ float ACC[1200];

__constant__ int JT_aoff[32] = {
    0,0,0,0,0,0,0,0,  8,8,8,8,8,8,  16,16,16,16,  24,24,
    0,8,16,24,  0,8,16,24,  32,  0,0,0 };
__constant__ int JT_boff[32] = {
    0,4,8,12,16,20,24,28,  8,12,16,20,24,28,  16,20,24,28,  24,28,
    32,32,32,32,  36,36,36,36,  36,  36,36,36 };
__constant__ int JT_kind[32] = {
    0,0,0,0,0,0,0,0, 0,0,0,0,0,0, 0,0,0,0, 0,0,
    1,1,1,1, 2,2,2,2, 3, 4,4,4 };

// smem: buf[2] 64 rows x 48 floats = 2 x 12288 B; epilogue overlays (32768 B)
#define BUFB 12288
#define SMEMSZ 32768

typedef unsigned long long u64;

static __device__ __forceinline__ uint32_t s2u(const void* p) {
    uint32_t a;
    asm("{ .reg .u64 t; cvta.to.shared.u64 t, %1; cvt.u32.u64 %0, t; }"
        : "=r"(a) : "l"(p));
    return a;
}
#define CP16(dst, src) \
    asm volatile("cp.async.cg.shared.global [%0], [%1], 16;" :: "r"(dst), "l"(src) : "memory")
#define CP_COMMIT() asm volatile("cp.async.commit_group;" ::: "memory")
#define CP_WAIT1()  asm volatile("cp.async.wait_group 1;" ::: "memory")
#define CP_WAIT0()  asm volatile("cp.async.wait_group 0;" ::: "memory")

static __device__ __forceinline__ void ffma2(u64& d, u64 a, u64 b) {
    asm("fma.rn.f32x2 %0, %1, %2, %0;" : "+l"(d) : "l"(a), "l"(b));
}
static __device__ __forceinline__ u64 dup2(float x) {
    u64 r; unsigned u = __float_as_uint(x);
    asm("mov.b64 %0, {%1, %1};" : "=l"(r) : "r"(u));
    return r;
}
static __device__ __forceinline__ void unpack2(u64 v, float& lo, float& hi) {
    unsigned a, b;
    asm("mov.b64 {%0, %1}, %2;" : "=r"(a), "=r"(b) : "l"(v));
    lo = __uint_as_float(a);
    hi = __uint_as_float(b);
}

__global__ void zero_acc_kernel() {
    int t = blockIdx.x * blockDim.x + threadIdx.x;
    if (t < 1200) ACC[t] = 0.0f;
}

// ---------------------------------------------------------------------------
__global__ __launch_bounds__(TPB, 2) void gram_kernel(
    const float* __restrict__ X, const float* __restrict__ Y,
    int N, int ntiles)
{
    extern __shared__ char smem[];
    const uint32_t sb = s2u(smem);
    const int tid = threadIdx.x;
    const int w   = tid >> 5;
    const int l   = tid & 31;

    // lane job -> constant-stride offsets inside the unified 48-float rows
    const int a_rel = w * 48 + JT_aoff[l];
    const int b_rel = w * 48 + JT_boff[l];

    u64 acc[4][4];
#pragma unroll
    for (int p = 0; p < 4; p++)
#pragma unroll
        for (int q = 0; q < 4; q++) acc[p][q] = 0ull;

    const int bx = blockIdx.x;
    const int nloc = (ntiles > bx) ? (ntiles - 1 - bx) / (int)gridDim.x + 1 : 0;

    // staging: 4 threads per row; xrow = tid>>2, quad xq = tid&3
    const int xrow = tid >> 2;
    const int xq   = tid & 3;

    auto stage = [&](int i) {
        const int p = i & 1;
        long long g = (long long)bx + (long long)i * gridDim.x;
        long long r = g * 64 + xrow;
        const int valid = (r < (long long)N);
        uint32_t dst = sb + p * BUFB + xrow * 192 + xq * 32;
        if (valid) {
            const float* src = X + r * 32 + xq * 8;
            CP16(dst, src);
            CP16(dst + 16, src + 4);
        } else {
            float* rowp = (float*)(smem + p * BUFB) + xrow * 48 + xq * 8;
            const float4 z4 = make_float4(0.f, 0.f, 0.f, 0.f);
            *(float4*)(rowp)     = z4;
            *(float4*)(rowp + 4) = z4;
        }
        if (xq == 0) {
            float* rowp = (float*)(smem + p * BUFB) + xrow * 48;
            if (valid) CP16(sb + p * BUFB + xrow * 192 + 128, Y + r * 4);
            else *(float4*)(rowp + 32) = make_float4(0.f, 0.f, 0.f, 0.f);
            *(float4*)(rowp + 36) = make_float4(valid ? 1.0f : 0.0f, 0.f, 0.f, 0.f);
        }
        CP_COMMIT();
    };

    if (nloc > 0) stage(0);

    for (int i = 0; i < nloc; i++) {
        const int p = i & 1;
        if (i + 1 < nloc) { stage(i + 1); CP_WAIT1(); } else { CP_WAIT0(); }
        __syncthreads();

        const float* ab = (const float*)(smem + p * BUFB) + a_rel;
        const float* bb = (const float*)(smem + p * BUFB) + b_rel;
#pragma unroll
        for (int k = 0; k < 8; k++) {
            ulonglong2 a01 = *(const ulonglong2*)(ab + k * 384);
            ulonglong2 a23 = *(const ulonglong2*)(ab + k * 384 + 4);
            float4     bv  = *(const float4*)(bb + k * 384);
            u64 ap[4] = {a01.x, a01.y, a23.x, a23.y};
            u64 bd[4] = {dup2(bv.x), dup2(bv.y), dup2(bv.z), dup2(bv.w)};
#pragma unroll
            for (int pp = 0; pp < 4; pp++)
#pragma unroll
                for (int q = 0; q < 4; q++) ffma2(acc[pp][q], ap[pp], bd[q]);
        }
        __syncthreads();
    }

    // ---- epilogue: stash per-lane accs, 8-warp reduce, atomic scatter ----
    u64* epi = (u64*)smem;
    u64* mine = epi + (w * 32 + l) * 16;
#pragma unroll
    for (int t = 0; t < 16; t++) mine[t] = acc[t >> 2][t & 3];
    __syncthreads();

    for (int s = tid; s < 512; s += TPB) {
        const int l2 = s >> 4, t = s & 15;
        const int kind = JT_kind[l2];
        if (kind == 4) continue;
        const int pp = t >> 2, qq = t & 3;
        if (kind >= 2 && qq != 0) continue;
        float lo = 0.f, hi = 0.f;
#pragma unroll
        for (int ww = 0; ww < 8; ww++) {
            float a, b;
            unpack2(epi[(ww * 32 + l2) * 16 + t], a, b);
            lo += a; hi += b;
        }
        const int i0 = JT_aoff[l2], j0 = JT_boff[l2];
        const int ii = i0 + 2 * pp;
        if (kind == 0) {
            atomicAdd(&ACC[ii * 32 + j0 + qq], lo);
            atomicAdd(&ACC[(ii + 1) * 32 + j0 + qq], hi);
        } else if (kind == 1) {
            atomicAdd(&ACC[1024 + ii * 4 + qq], lo);
            atomicAdd(&ACC[1024 + (ii + 1) * 4 + qq], hi);
        } else if (kind == 2) {
            atomicAdd(&ACC[1152 + ii], lo);
            atomicAdd(&ACC[1153 + ii], hi);
        } else {  // kind 3: a = (y0,y1)(y2,y3)(v,0)(0,0), b = (v,0,0,0)
            if (pp < 2) {
                atomicAdd(&ACC[1184 + 2 * pp], lo);
                atomicAdd(&ACC[1185 + 2 * pp], hi);
            } else if (pp == 2) {
                atomicAdd(&ACC[1188], lo);   // count = sum v*v
            }
        }
    }
}

// ---------------------------------------------------------------------------
__global__ __launch_bounds__(256) void solve_kernel(float* __restrict__ out)
{
    __shared__ float G[33 * 33];
    __shared__ float c[132];
    __shared__ float Z[132];
    __shared__ float rowsum[33];
    __shared__ float stepSh;

    const int tid = threadIdx.x;
    // triangle coverage: tile (i>>3, j>>2) computed iff (j|3) >= (i&~7)
    for (int e = tid; e < 33 * 33; e += 256) {
        int i = e / 33, j = e % 33;
        float v;
        if (i < 32 && j < 32)
            v = ((j | 3) >= (i & ~7)) ? ACC[i * 32 + j] : ACC[j * 32 + i];
        else if (i < 32)      v = ACC[1152 + i];
        else if (j < 32)      v = ACC[1152 + j];
        else                  v = ACC[1188];
        G[e] = v;
    }
    if (tid < 132) {
        int i = tid >> 2, m = tid & 3;
        c[tid] = (i < 32) ? ACC[1024 + tid] : ACC[1184 + m];
        Z[tid] = 0.0f;
    }
    __syncthreads();

    if (tid < 33) {
        float s = 0.f;
        for (int j = 0; j < 33; j++) s += fabsf(G[tid * 33 + j]);
        rowsum[tid] = s;
    }
    __syncthreads();
    if (tid == 0) {
        float L = 0.f;
        for (int i = 0; i < 33; i++) L = fmaxf(L, rowsum[i]);
        stepSh = 1.0f / L;
    }
    __syncthreads();
    const float step = stepSh;

    const int i = tid >> 2, m = tid & 3;
    for (int it = 0; it < PGD_ITERS; it++) {
        float zn = 0.f;
        if (tid < 132) {
            float dot = 0.f;
#pragma unroll
            for (int j = 0; j < 33; j++) dot += G[i * 33 + j] * Z[j * 4 + m];
            zn = Z[tid] - step * (dot - c[tid]);
            if (i < 32) zn = fmaxf(zn, 0.0f);
        }
        __syncthreads();
        if (tid < 132) Z[tid] = zn;
        __syncthreads();
    }
    if (tid < 128) out[tid] = Z[tid];
}

// ---------------------------------------------------------------------------
extern "C" void kernel_launch(void* const* d_in, const int* in_sizes, int n_in,
                              void* d_out, int out_size)
{
    const float* X = (const float*)d_in[0];
    const float* Y = (const float*)d_in[1];
    const int N = in_sizes[0] / 32;
    const int ntiles = (N + 63) / 64;

    cudaFuncSetAttribute(gram_kernel,
                         cudaFuncAttributeMaxDynamicSharedMemorySize, SMEMSZ);

    zero_acc_kernel<<<5, 256>>>();
    gram_kernel<<<NCTA, TPB, SMEMSZ>>>(X, Y, N, ntiles);
    solve_kernel<<<1, 256>>>((float*)d_out);
}

// round 13
// speedup vs baseline: 1.0830x; 1.0830x over previous
#include <cuda_runtime.h>
#include <cstdint>

// ============================================================================
// NNLS via normal equations. R4 skeleton (best: 133.9us), c-pass packed:
//   - G pass unchanged: 8x4 f32x2 register blocks, row-uniform warps.
//   - c pass: 2x FFMA2 (packed y pairs) + FFMA-imm colsum per row.
//   - ysum moved to a separate tiny DRAM-bound kernel (was predicated
//     lane-0 FMAs occupying the whole warp's fma pipe).
// Then tiny projected-gradient QP solve (G ~ N*I, kappa ~ 1.02).
// ============================================================================

#define TPB 256
#define NCTA 296
#define TROWS 64
#define PGD_ITERS 48

// ACC layout:
//   [0..1023]    : G[i][j]   [1024..1055] : colsum[i]
//   [1056..1183] : c[i][m]   [1184..1187] : ysum[m]
__device__ float ACC[1280];

// ---- dynamic smem layout (bytes) ----
#define RAWX_OFF 0          // 2 x [64][32] f32 = 2 x 8192
#define RAWY_OFF 16384      // 2 x [64][4]  f32 = 2 x 1024
#define SG_OFF   18432      // 8 x 1024 f32 = 32768
#define SCP_OFF  51200      // 8 x 32 x 4 f32 = 4096
#define SXP_OFF  55296      // 8 x 32 f32 = 1024
#define SMEMSZ   56320

typedef unsigned long long u64;

static __device__ __forceinline__ uint32_t s2u(const void* p) {
    uint32_t a;
    asm("{ .reg .u64 t; cvta.to.shared.u64 t, %1; cvt.u32.u64 %0, t; }"
        : "=r"(a) : "l"(p));
    return a;
}

#define CP16(dst, src) \
    asm volatile("cp.async.cg.shared.global [%0], [%1], 16;" :: "r"(dst), "l"(src) : "memory")
#define CP_COMMIT() asm volatile("cp.async.commit_group;" ::: "memory")
#define CP_WAIT1()  asm volatile("cp.async.wait_group 1;" ::: "memory")
#define CP_WAIT0()  asm volatile("cp.async.wait_group 0;" ::: "memory")

static __device__ __forceinline__ void ffma2(u64& d, u64 a, u64 b) {
    asm("fma.rn.f32x2 %0, %1, %2, %0;" : "+l"(d) : "l"(a), "l"(b));
}
static __device__ __forceinline__ u64 dup2(float x) {
    u64 r; unsigned u = __float_as_uint(x);
    asm("mov.b64 %0, {%1, %1};" : "=l"(r) : "r"(u));
    return r;
}
static __device__ __forceinline__ void unpack2(u64 v, float& lo, float& hi) {
    unsigned a, b;
    asm("mov.b64 {%0, %1}, %2;" : "=r"(a), "=r"(b) : "l"(v));
    lo = __uint_as_float(a);
    hi = __uint_as_float(b);
}
static __device__ __forceinline__ void add_imm1(float& s, float x) {
    // colsum accumulate as FFMA with immediate multiplier (rt_SMSP = 1)
    asm("fma.rn.f32 %0, %1, 0f3F800000, %0;" : "+f"(s) : "f"(x));
}

// ---------------------------------------------------------------------------
__global__ void zero_acc_kernel() {
    int t = blockIdx.x * blockDim.x + threadIdx.x;
    if (t < 1280) ACC[t] = 0.0f;
}

// ---------------------------------------------------------------------------
// ysum[m] = sum_r Y[r][m]  (DRAM-bound, ~5us)
__global__ __launch_bounds__(256) void ysum_kernel(const float* __restrict__ Y, int N)
{
    __shared__ float red[8][4];
    const int tid = threadIdx.x;
    const float4* Y4 = (const float4*)Y;
    float4 s = make_float4(0.f, 0.f, 0.f, 0.f);
    for (long long i = (long long)blockIdx.x * 256 + tid; i < N;
         i += (long long)gridDim.x * 256) {
        float4 v = Y4[i];
        s.x += v.x; s.y += v.y; s.z += v.z; s.w += v.w;
    }
#pragma unroll
    for (int o = 16; o > 0; o >>= 1) {
        s.x += __shfl_down_sync(0xFFFFFFFFu, s.x, o);
        s.y += __shfl_down_sync(0xFFFFFFFFu, s.y, o);
        s.z += __shfl_down_sync(0xFFFFFFFFu, s.z, o);
        s.w += __shfl_down_sync(0xFFFFFFFFu, s.w, o);
    }
    const int w = tid >> 5, l = tid & 31;
    if (l == 0) { red[w][0] = s.x; red[w][1] = s.y; red[w][2] = s.z; red[w][3] = s.w; }
    __syncthreads();
    if (tid < 4) {
        float t0 = 0.f;
#pragma unroll
        for (int ww = 0; ww < 8; ww++) t0 += red[ww][tid];
        atomicAdd(&ACC[1184 + tid], t0);
    }
}

// ---------------------------------------------------------------------------
__global__ __launch_bounds__(TPB, 2) void gram_kernel(
    const float* __restrict__ X, const float* __restrict__ Y,
    int ntiles, int N)
{
    extern __shared__ char smem[];
    const uint32_t sb = s2u(smem);

    const int tid = threadIdx.x;
    const int w   = tid >> 5;      // warp 0..7 (row-uniform owner: rows r%8==w)
    const int l   = tid & 31;
    const int bi  = (l >> 2) & 3;  // i block: i0 = 8*bi
    const int bj  = l & 3;         // j block
    const int jh  = l >> 4;        // j half: j0 = 8*bj + 4*jh
    const int jq4 = 2 * bj + jh;   // float4 column of the j vector

    u64 acc[4][4];
#pragma unroll
    for (int p = 0; p < 4; p++)
#pragma unroll
        for (int q = 0; q < 4; q++) acc[p][q] = 0ull;

    u64 cacc01 = 0ull, cacc23 = 0ull;   // c[i][0..1], c[i][2..3] packed
    float sxacc = 0.f;

    const float4* X4 = (const float4*)X;
    const float4* Y4 = (const float4*)Y;
    const long long total4 = (long long)N * 8;
    const int nloc = (ntiles > (int)blockIdx.x)
                     ? (ntiles - 1 - (int)blockIdx.x) / (int)gridDim.x + 1 : 0;

    auto stage = [&](int i) {
        long long g = (long long)blockIdx.x + (long long)i * gridDim.x;
        int p = i & 1;
        long long gi = g * 512 + tid;
        uint32_t dx = sb + RAWX_OFF + p * 8192 + tid * 16;
        float4 z = make_float4(0.f, 0.f, 0.f, 0.f);
        if (gi < total4) CP16(dx, X4 + gi);
        else *(float4*)(smem + RAWX_OFF + p * 8192 + tid * 16) = z;
        if (gi + 256 < total4) CP16(dx + 4096, X4 + gi + 256);
        else *(float4*)(smem + RAWX_OFF + p * 8192 + tid * 16 + 4096) = z;
        if (tid < 64) {
            long long gy = g * 64 + tid;
            if (gy < N) CP16(sb + RAWY_OFF + p * 1024 + tid * 16, Y4 + gy);
            else *(float4*)(smem + RAWY_OFF + p * 1024 + tid * 16) = z;
        }
        CP_COMMIT();
    };

    if (nloc > 0) stage(0);

    for (int i = 0; i < nloc; i++) {
        const int p = i & 1;
        if (i + 1 < nloc) { stage(i + 1); CP_WAIT1(); } else { CP_WAIT0(); }
        __syncthreads();

        const float4*     rx  = (const float4*)(smem + RAWX_OFF + p * 8192);
        const ulonglong2* rxu = (const ulonglong2*)rx;
        const float*      sx  = (const float*)rx;
        const ulonglong2* syu = (const ulonglong2*)(smem + RAWY_OFF + p * 1024);

        // ---- G pass: rows r = w + 8k (broadcast LDS, 16 FFMA2/row) ----
#pragma unroll
        for (int k = 0; k < 8; k++) {
            const int r = w + 8 * k;
            ulonglong2 ia = rxu[r * 8 + 2 * bi];
            ulonglong2 ib = rxu[r * 8 + 2 * bi + 1];
            float4     jv = rx [r * 8 + jq4];
            u64 ap[4] = {ia.x, ia.y, ib.x, ib.y};
            u64 bd[4] = {dup2(jv.x), dup2(jv.y), dup2(jv.z), dup2(jv.w)};
#pragma unroll
            for (int pp = 0; pp < 4; pp++)
#pragma unroll
                for (int q = 0; q < 4; q++) ffma2(acc[pp][q], ap[pp], bd[q]);
        }

        // ---- c pass (packed): rows r = w + 8k; lane l = column i ----
#pragma unroll
        for (int k = 0; k < 8; k++) {
            const int r = w + 8 * k;
            float x = sx[r * 32 + l];
            ulonglong2 yp = syu[r];           // (y0,y1),(y2,y3)
            u64 xd = dup2(x);
            ffma2(cacc01, xd, yp.x);
            ffma2(cacc23, xd, yp.y);
            add_imm1(sxacc, x);               // FFMA-imm, rt=1
        }
        __syncthreads();
    }

    // ---- epilogue: per-warp G slice into smem, then reduce + atomics ----
    {
        float* mg = (float*)(smem + SG_OFF) + w * 1024;
        const int j0 = 8 * bj + 4 * jh;
#pragma unroll
        for (int pp = 0; pp < 4; pp++) {
            const int i0 = 8 * bi + 2 * pp;
#pragma unroll
            for (int q = 0; q < 4; q++) {
                float lo, hi;
                unpack2(acc[pp][q], lo, hi);
                mg[i0 * 32 + j0 + q]       = lo;
                mg[(i0 + 1) * 32 + j0 + q] = hi;
            }
        }
        float* scp = (float*)(smem + SCP_OFF) + w * 128;
        float c0, c1, c2, c3;
        unpack2(cacc01, c0, c1);
        unpack2(cacc23, c2, c3);
        scp[l * 4 + 0] = c0; scp[l * 4 + 1] = c1;
        scp[l * 4 + 2] = c2; scp[l * 4 + 3] = c3;
        ((float*)(smem + SXP_OFF))[w * 32 + l] = sxacc;
    }
    __syncthreads();

    {
        const float* sg = (const float*)(smem + SG_OFF);
        for (int e = tid; e < 1024; e += TPB) {
            float s = 0.f;
#pragma unroll
            for (int ww = 0; ww < 8; ww++) s += sg[ww * 1024 + e];
            atomicAdd(&ACC[e], s);
        }
        if (tid < 128) {
            const float* scp = (const float*)(smem + SCP_OFF);
            float s = 0.f;
#pragma unroll
            for (int ww = 0; ww < 8; ww++) s += scp[ww * 128 + tid];
            atomicAdd(&ACC[1056 + tid], s);
        }
        if (tid < 32) {
            const float* sxp = (const float*)(smem + SXP_OFF);
            float s = 0.f;
#pragma unroll
            for (int ww = 0; ww < 8; ww++) s += sxp[ww * 32 + tid];
            atomicAdd(&ACC[1024 + tid], s);
        }
    }
}

// ---------------------------------------------------------------------------
__global__ __launch_bounds__(256) void solve_kernel(float* __restrict__ out, float Nf)
{
    __shared__ float G[33 * 33];
    __shared__ float c[132];
    __shared__ float Z[132];
    __shared__ float rowsum[33];
    __shared__ float stepSh;

    const int tid = threadIdx.x;
    for (int e = tid; e < 1024; e += 256) {
        int i = e >> 5, j = e & 31;
        G[i * 33 + j] = ACC[e];
    }
    if (tid < 32) {
        float s = ACC[1024 + tid];
        G[tid * 33 + 32] = s;
        G[32 * 33 + tid] = s;
    }
    if (tid == 0) G[32 * 33 + 32] = Nf;
    if (tid < 128) c[tid] = ACC[1056 + tid];
    if (tid >= 128 && tid < 132) c[tid] = ACC[1184 + (tid - 128)];
    if (tid < 132) Z[tid] = 0.0f;
    __syncthreads();

    if (tid < 33) {
        float s = 0.f;
        for (int j = 0; j < 33; j++) s += fabsf(G[tid * 33 + j]);
        rowsum[tid] = s;
    }
    __syncthreads();
    if (tid == 0) {
        float L = 0.f;
        for (int i = 0; i < 33; i++) L = fmaxf(L, rowsum[i]);
        stepSh = 1.0f / L;
    }
    __syncthreads();
    const float step = stepSh;

    const int i = tid >> 2, m = tid & 3;
    for (int it = 0; it < PGD_ITERS; it++) {
        float zn = 0.f;
        if (tid < 132) {
            float dot = 0.f;
#pragma unroll
            for (int j = 0; j < 33; j++) dot += G[i * 33 + j] * Z[j * 4 + m];
            zn = Z[tid] - step * (dot - c[tid]);
            if (i < 32) zn = fmaxf(zn, 0.0f);
        }
        __syncthreads();
        if (tid < 132) Z[tid] = zn;
        __syncthreads();
    }
    if (tid < 128) out[tid] = Z[tid];
}

// ---------------------------------------------------------------------------
extern "C" void kernel_launch(void* const* d_in, const int* in_sizes, int n_in,
                              void* d_out, int out_size)
{
    const float* X = (const float*)d_in[0];
    const float* Y = (const float*)d_in[1];
    const int N = in_sizes[0] / 32;
    const int ntiles = (N + TROWS - 1) / TROWS;

    cudaFuncSetAttribute(gram_kernel,
                         cudaFuncAttributeMaxDynamicSharedMemorySize, SMEMSZ);

    zero_acc_kernel<<<5, 256>>>();
    ysum_kernel<<<NCTA, 256>>>(Y, N);
    gram_kernel<<<NCTA, TPB, SMEMSZ>>>(X, Y, ntiles, N);
    solve_kernel<<<1, 256>>>((float*)d_out, (float)N);
}

// round 14
// speedup vs baseline: 1.1191x; 1.0333x over previous
#include <cuda_runtime.h>
#include <cstdint>

// ============================================================================
// NNLS via normal equations. R12 gram (best-class), serial chain compressed:
//   - init kernel: zero ACC + ysum partials (one launch, full-BW Y read)
//   - gram kernel: unchanged (FFMA2 8x4 blocks + packed c-pass)
//   - solve kernel: 24 PGD iters, 1 barrier/iter (double-buffered Z),
//     reduces ysum partials inline.
// ============================================================================

#define TPB 256
#define NCTA 296
#define TROWS 64
#define PGD_ITERS 24

// ACC: [0..1023] G[i][j], [1024..1055] colsum[i], [1056..1183] c[i][m]
__device__ float ACC[1184];
__device__ float YSP[NCTA * 4];   // per-block ysum partials

// ---- dynamic smem layout (bytes) ----
#define RAWX_OFF 0          // 2 x [64][32] f32 = 2 x 8192
#define RAWY_OFF 16384      // 2 x [64][4]  f32 = 2 x 1024
#define SG_OFF   18432      // 8 x 1024 f32 = 32768
#define SCP_OFF  51200      // 8 x 32 x 4 f32 = 4096
#define SXP_OFF  55296      // 8 x 32 f32 = 1024
#define SMEMSZ   56320

typedef unsigned long long u64;

static __device__ __forceinline__ uint32_t s2u(const void* p) {
    uint32_t a;
    asm("{ .reg .u64 t; cvta.to.shared.u64 t, %1; cvt.u32.u64 %0, t; }"
        : "=r"(a) : "l"(p));
    return a;
}

#define CP16(dst, src) \
    asm volatile("cp.async.cg.shared.global [%0], [%1], 16;" :: "r"(dst), "l"(src) : "memory")
#define CP_COMMIT() asm volatile("cp.async.commit_group;" ::: "memory")
#define CP_WAIT1()  asm volatile("cp.async.wait_group 1;" ::: "memory")
#define CP_WAIT0()  asm volatile("cp.async.wait_group 0;" ::: "memory")

static __device__ __forceinline__ void ffma2(u64& d, u64 a, u64 b) {
    asm("fma.rn.f32x2 %0, %1, %2, %0;" : "+l"(d) : "l"(a), "l"(b));
}
static __device__ __forceinline__ u64 dup2(float x) {
    u64 r; unsigned u = __float_as_uint(x);
    asm("mov.b64 %0, {%1, %1};" : "=l"(r) : "r"(u));
    return r;
}
static __device__ __forceinline__ void unpack2(u64 v, float& lo, float& hi) {
    unsigned a, b;
    asm("mov.b64 {%0, %1}, %2;" : "=r"(a), "=r"(b) : "l"(v));
    lo = __uint_as_float(a);
    hi = __uint_as_float(b);
}
static __device__ __forceinline__ void add_imm1(float& s, float x) {
    asm("fma.rn.f32 %0, %1, 0f3F800000, %0;" : "+f"(s) : "f"(x));
}

// ---------------------------------------------------------------------------
// init: zero ACC + per-block ysum partials (grid-stride over Y, full BW)
__global__ __launch_bounds__(256) void init_kernel(const float* __restrict__ Y, int N)
{
    __shared__ float red[8][4];
    const int tid = threadIdx.x;
    const int bx  = blockIdx.x;

    const int g = bx * 256 + tid;
    if (g < 1184) ACC[g] = 0.0f;

    const float4* Y4 = (const float4*)Y;
    float4 s = make_float4(0.f, 0.f, 0.f, 0.f);
    for (long long i = (long long)bx * 256 + tid; i < N;
         i += (long long)NCTA * 256) {
        float4 v = Y4[i];
        s.x += v.x; s.y += v.y; s.z += v.z; s.w += v.w;
    }
#pragma unroll
    for (int o = 16; o > 0; o >>= 1) {
        s.x += __shfl_down_sync(0xFFFFFFFFu, s.x, o);
        s.y += __shfl_down_sync(0xFFFFFFFFu, s.y, o);
        s.z += __shfl_down_sync(0xFFFFFFFFu, s.z, o);
        s.w += __shfl_down_sync(0xFFFFFFFFu, s.w, o);
    }
    const int w = tid >> 5, l = tid & 31;
    if (l == 0) { red[w][0] = s.x; red[w][1] = s.y; red[w][2] = s.z; red[w][3] = s.w; }
    __syncthreads();
    if (tid < 4) {
        float t0 = 0.f;
#pragma unroll
        for (int ww = 0; ww < 8; ww++) t0 += red[ww][tid];
        YSP[bx * 4 + tid] = t0;
    }
}

// ---------------------------------------------------------------------------
__global__ __launch_bounds__(TPB, 2) void gram_kernel(
    const float* __restrict__ X, const float* __restrict__ Y,
    int ntiles, int N)
{
    extern __shared__ char smem[];
    const uint32_t sb = s2u(smem);

    const int tid = threadIdx.x;
    const int w   = tid >> 5;
    const int l   = tid & 31;
    const int bi  = (l >> 2) & 3;
    const int bj  = l & 3;
    const int jh  = l >> 4;
    const int jq4 = 2 * bj + jh;

    u64 acc[4][4];
#pragma unroll
    for (int p = 0; p < 4; p++)
#pragma unroll
        for (int q = 0; q < 4; q++) acc[p][q] = 0ull;

    u64 cacc01 = 0ull, cacc23 = 0ull;
    float sxacc = 0.f;

    const float4* X4 = (const float4*)X;
    const float4* Y4 = (const float4*)Y;
    const long long total4 = (long long)N * 8;
    const int nloc = (ntiles > (int)blockIdx.x)
                     ? (ntiles - 1 - (int)blockIdx.x) / (int)gridDim.x + 1 : 0;

    auto stage = [&](int i) {
        long long g = (long long)blockIdx.x + (long long)i * gridDim.x;
        int p = i & 1;
        long long gi = g * 512 + tid;
        uint32_t dx = sb + RAWX_OFF + p * 8192 + tid * 16;
        float4 z = make_float4(0.f, 0.f, 0.f, 0.f);
        if (gi < total4) CP16(dx, X4 + gi);
        else *(float4*)(smem + RAWX_OFF + p * 8192 + tid * 16) = z;
        if (gi + 256 < total4) CP16(dx + 4096, X4 + gi + 256);
        else *(float4*)(smem + RAWX_OFF + p * 8192 + tid * 16 + 4096) = z;
        if (tid < 64) {
            long long gy = g * 64 + tid;
            if (gy < N) CP16(sb + RAWY_OFF + p * 1024 + tid * 16, Y4 + gy);
            else *(float4*)(smem + RAWY_OFF + p * 1024 + tid * 16) = z;
        }
        CP_COMMIT();
    };

    if (nloc > 0) stage(0);

    for (int i = 0; i < nloc; i++) {
        const int p = i & 1;
        if (i + 1 < nloc) { stage(i + 1); CP_WAIT1(); } else { CP_WAIT0(); }
        __syncthreads();

        const float4*     rx  = (const float4*)(smem + RAWX_OFF + p * 8192);
        const ulonglong2* rxu = (const ulonglong2*)rx;
        const float*      sx  = (const float*)rx;
        const ulonglong2* syu = (const ulonglong2*)(smem + RAWY_OFF + p * 1024);

#pragma unroll
        for (int k = 0; k < 8; k++) {
            const int r = w + 8 * k;
            ulonglong2 ia = rxu[r * 8 + 2 * bi];
            ulonglong2 ib = rxu[r * 8 + 2 * bi + 1];
            float4     jv = rx [r * 8 + jq4];
            u64 ap[4] = {ia.x, ia.y, ib.x, ib.y};
            u64 bd[4] = {dup2(jv.x), dup2(jv.y), dup2(jv.z), dup2(jv.w)};
#pragma unroll
            for (int pp = 0; pp < 4; pp++)
#pragma unroll
                for (int q = 0; q < 4; q++) ffma2(acc[pp][q], ap[pp], bd[q]);
        }

#pragma unroll
        for (int k = 0; k < 8; k++) {
            const int r = w + 8 * k;
            float x = sx[r * 32 + l];
            ulonglong2 yp = syu[r];
            u64 xd = dup2(x);
            ffma2(cacc01, xd, yp.x);
            ffma2(cacc23, xd, yp.y);
            add_imm1(sxacc, x);
        }
        __syncthreads();
    }

    {
        float* mg = (float*)(smem + SG_OFF) + w * 1024;
        const int j0 = 8 * bj + 4 * jh;
#pragma unroll
        for (int pp = 0; pp < 4; pp++) {
            const int i0 = 8 * bi + 2 * pp;
#pragma unroll
            for (int q = 0; q < 4; q++) {
                float lo, hi;
                unpack2(acc[pp][q], lo, hi);
                mg[i0 * 32 + j0 + q]       = lo;
                mg[(i0 + 1) * 32 + j0 + q] = hi;
            }
        }
        float* scp = (float*)(smem + SCP_OFF) + w * 128;
        float c0, c1, c2, c3;
        unpack2(cacc01, c0, c1);
        unpack2(cacc23, c2, c3);
        scp[l * 4 + 0] = c0; scp[l * 4 + 1] = c1;
        scp[l * 4 + 2] = c2; scp[l * 4 + 3] = c3;
        ((float*)(smem + SXP_OFF))[w * 32 + l] = sxacc;
    }
    __syncthreads();

    {
        const float* sg = (const float*)(smem + SG_OFF);
        for (int e = tid; e < 1024; e += TPB) {
            float s = 0.f;
#pragma unroll
            for (int ww = 0; ww < 8; ww++) s += sg[ww * 1024 + e];
            atomicAdd(&ACC[e], s);
        }
        if (tid < 128) {
            const float* scp = (const float*)(smem + SCP_OFF);
            float s = 0.f;
#pragma unroll
            for (int ww = 0; ww < 8; ww++) s += scp[ww * 128 + tid];
            atomicAdd(&ACC[1056 + tid], s);
        }
        if (tid < 32) {
            const float* sxp = (const float*)(smem + SXP_OFF);
            float s = 0.f;
#pragma unroll
            for (int ww = 0; ww < 8; ww++) s += sxp[ww * 32 + tid];
            atomicAdd(&ACC[1024 + tid], s);
        }
    }
}

// ---------------------------------------------------------------------------
__global__ __launch_bounds__(256) void solve_kernel(float* __restrict__ out, float Nf)
{
    __shared__ float G[33 * 33];
    __shared__ float c[132];
    __shared__ float Zb[2][132];
    __shared__ float rowsum[33];
    __shared__ float stepSh;
    __shared__ float ysred[4][64];

    const int tid = threadIdx.x;

    // reduce ysum partials (296 x 4)
    {
        const int m = tid & 3, ch = tid >> 2;   // 64 chunks per m
        float s = 0.f;
        for (int j = ch; j < NCTA; j += 64) s += YSP[j * 4 + m];
        ysred[m][ch] = s;
    }

    for (int e = tid; e < 1024; e += 256) {
        int i = e >> 5, j = e & 31;
        G[i * 33 + j] = ACC[e];
    }
    if (tid < 32) {
        float s = ACC[1024 + tid];
        G[tid * 33 + 32] = s;
        G[32 * 33 + tid] = s;
    }
    if (tid == 0) G[32 * 33 + 32] = Nf;
    if (tid < 128) c[tid] = ACC[1056 + tid];
    if (tid < 132) { Zb[0][tid] = 0.0f; }
    __syncthreads();

    if (tid < 4) {
        float s = 0.f;
#pragma unroll
        for (int k = 0; k < 64; k++) s += ysred[tid][k];
        c[128 + tid] = s;
    }
    if (tid < 33) {
        float s = 0.f;
        for (int j = 0; j < 33; j++) s += fabsf(G[tid * 33 + j]);
        rowsum[tid] = s;
    }
    __syncthreads();
    if (tid == 0) {
        float L = 0.f;
        for (int i = 0; i < 33; i++) L = fmaxf(L, rowsum[i]);
        stepSh = 1.0f / L;
    }
    __syncthreads();
    const float step = stepSh;

    const int i = tid >> 2, m = tid & 3;
    int cur = 0;
    for (int it = 0; it < PGD_ITERS; it++) {
        if (tid < 132) {
            const float* Z = Zb[cur];
            float dot = 0.f;
#pragma unroll
            for (int j = 0; j < 33; j++) dot += G[i * 33 + j] * Z[j * 4 + m];
            float zn = Z[tid] - step * (dot - c[tid]);
            if (i < 32) zn = fmaxf(zn, 0.0f);
            Zb[cur ^ 1][tid] = zn;
        }
        __syncthreads();
        cur ^= 1;
    }
    if (tid < 128) out[tid] = Zb[cur][tid];
}

// ---------------------------------------------------------------------------
extern "C" void kernel_launch(void* const* d_in, const int* in_sizes, int n_in,
                              void* d_out, int out_size)
{
    const float* X = (const float*)d_in[0];
    const float* Y = (const float*)d_in[1];
    const int N = in_sizes[0] / 32;
    const int ntiles = (N + TROWS - 1) / TROWS;

    cudaFuncSetAttribute(gram_kernel,
                         cudaFuncAttributeMaxDynamicSharedMemorySize, SMEMSZ);

    init_kernel<<<NCTA, 256>>>(Y, N);
    gram_kernel<<<NCTA, TPB, SMEMSZ>>>(X, Y, ntiles, N);
    solve_kernel<<<1, 256>>>((float*)d_out, (float)N);
}

// round 17
// speedup vs baseline: 1.1916x; 1.0648x over previous
#include <cuda_runtime.h>
#include <cstdint>

// ============================================================================
// NNLS via normal equations.
//   init : zero ACC + ysum partials (unroll-4, MLP>=4, DRAM-bound)
//   gram : FFMA2 8x4 register blocks + packed c-pass, TRIPLE-buffered
//          cp.async pipeline with ONE barrier per tile.
//          (R15 bug fixed: wait_group depth 1, not 2 -- at iter i the
//           committed groups are 0..i+1, so allowing 2 outstanding left
//           stage(i) itself incomplete.)
//   solve: 16 PGD iters, 1 barrier/iter (double-buffered Z).
// ============================================================================

#define TPB 256
#define NCTA 296
#define TROWS 64
#define PGD_ITERS 16

// ACC: [0..1023] G[i][j], [1024..1055] colsum[i], [1056..1183] c[i][m]
__device__ float ACC[1184];
__device__ float YSP[NCTA * 4];   // per-block ysum partials

// ---- dynamic smem layout (bytes) ----
#define RAWX_OFF 0          // 3 x [64][32] f32 = 3 x 8192 = 24576
#define RAWY_OFF 24576      // 3 x [64][4]  f32 = 3 x 1024 = 3072
#define SG_OFF   27648      // 8 x 1024 f32 = 32768
#define SCP_OFF  60416      // 8 x 32 x 4 f32 = 4096
#define SXP_OFF  64512      // 8 x 32 f32 = 1024
#define SMEMSZ   65536

typedef unsigned long long u64;

static __device__ __forceinline__ uint32_t s2u(const void* p) {
    uint32_t a;
    asm("{ .reg .u64 t; cvta.to.shared.u64 t, %1; cvt.u32.u64 %0, t; }"
        : "=r"(a) : "l"(p));
    return a;
}

#define CP16(dst, src) \
    asm volatile("cp.async.cg.shared.global [%0], [%1], 16;" :: "r"(dst), "l"(src) : "memory")
#define CP_COMMIT() asm volatile("cp.async.commit_group;" ::: "memory")
#define CP_WAIT1()  asm volatile("cp.async.wait_group 1;" ::: "memory")
#define CP_WAIT0()  asm volatile("cp.async.wait_group 0;" ::: "memory")

static __device__ __forceinline__ void ffma2(u64& d, u64 a, u64 b) {
    asm("fma.rn.f32x2 %0, %1, %2, %0;" : "+l"(d) : "l"(a), "l"(b));
}
static __device__ __forceinline__ u64 dup2(float x) {
    u64 r; unsigned u = __float_as_uint(x);
    asm("mov.b64 %0, {%1, %1};" : "=l"(r) : "r"(u));
    return r;
}
static __device__ __forceinline__ void unpack2(u64 v, float& lo, float& hi) {
    unsigned a, b;
    asm("mov.b64 {%0, %1}, %2;" : "=r"(a), "=r"(b) : "l"(v));
    lo = __uint_as_float(a);
    hi = __uint_as_float(b);
}
static __device__ __forceinline__ void add_imm1(float& s, float x) {
    asm("fma.rn.f32 %0, %1, 0f3F800000, %0;" : "+f"(s) : "f"(x));
}

// ---------------------------------------------------------------------------
// init: zero ACC + per-block ysum partials (unroll-4, 4 indep accumulators)
__global__ __launch_bounds__(256) void init_kernel(const float* __restrict__ Y, int N)
{
    __shared__ float red[8][4];
    const int tid = threadIdx.x;
    const int bx  = blockIdx.x;

    const int g = bx * 256 + tid;
    if (g < 1184) ACC[g] = 0.0f;

    const float4* Y4 = (const float4*)Y;
    float4 s0 = make_float4(0.f, 0.f, 0.f, 0.f);
    float4 s1 = s0, s2 = s0, s3 = s0;
    const long long stride = (long long)NCTA * 256;
    long long i = (long long)bx * 256 + tid;
    for (; i + 3 * stride < N; i += 4 * stride) {
        float4 v0 = Y4[i];
        float4 v1 = Y4[i + stride];
        float4 v2 = Y4[i + 2 * stride];
        float4 v3 = Y4[i + 3 * stride];
        s0.x += v0.x; s0.y += v0.y; s0.z += v0.z; s0.w += v0.w;
        s1.x += v1.x; s1.y += v1.y; s1.z += v1.z; s1.w += v1.w;
        s2.x += v2.x; s2.y += v2.y; s2.z += v2.z; s2.w += v2.w;
        s3.x += v3.x; s3.y += v3.y; s3.z += v3.z; s3.w += v3.w;
    }
    for (; i < N; i += stride) {
        float4 v = Y4[i];
        s0.x += v.x; s0.y += v.y; s0.z += v.z; s0.w += v.w;
    }
    s0.x += s1.x + s2.x + s3.x;
    s0.y += s1.y + s2.y + s3.y;
    s0.z += s1.z + s2.z + s3.z;
    s0.w += s1.w + s2.w + s3.w;
#pragma unroll
    for (int o = 16; o > 0; o >>= 1) {
        s0.x += __shfl_down_sync(0xFFFFFFFFu, s0.x, o);
        s0.y += __shfl_down_sync(0xFFFFFFFFu, s0.y, o);
        s0.z += __shfl_down_sync(0xFFFFFFFFu, s0.z, o);
        s0.w += __shfl_down_sync(0xFFFFFFFFu, s0.w, o);
    }
    const int w = tid >> 5, l = tid & 31;
    if (l == 0) { red[w][0] = s0.x; red[w][1] = s0.y; red[w][2] = s0.z; red[w][3] = s0.w; }
    __syncthreads();
    if (tid < 4) {
        float t0 = 0.f;
#pragma unroll
        for (int ww = 0; ww < 8; ww++) t0 += red[ww][tid];
        YSP[bx * 4 + tid] = t0;
    }
}

// ---------------------------------------------------------------------------
__global__ __launch_bounds__(TPB, 2) void gram_kernel(
    const float* __restrict__ X, const float* __restrict__ Y,
    int ntiles, int N)
{
    extern __shared__ char smem[];
    const uint32_t sb = s2u(smem);

    const int tid = threadIdx.x;
    const int w   = tid >> 5;
    const int l   = tid & 31;
    const int bi  = (l >> 2) & 3;
    const int bj  = l & 3;
    const int jh  = l >> 4;
    const int jq4 = 2 * bj + jh;

    u64 acc[4][4];
#pragma unroll
    for (int p = 0; p < 4; p++)
#pragma unroll
        for (int q = 0; q < 4; q++) acc[p][q] = 0ull;

    u64 cacc01 = 0ull, cacc23 = 0ull;
    float sxacc = 0.f;

    const float4* X4 = (const float4*)X;
    const float4* Y4 = (const float4*)Y;
    const long long total4 = (long long)N * 8;
    const int nloc = (ntiles > (int)blockIdx.x)
                     ? (ntiles - 1 - (int)blockIdx.x) / (int)gridDim.x + 1 : 0;

    auto stage = [&](int i) {
        long long g = (long long)blockIdx.x + (long long)i * gridDim.x;
        int p = i % 3;
        long long gi = g * 512 + tid;
        uint32_t dx = sb + RAWX_OFF + p * 8192 + tid * 16;
        float4 z = make_float4(0.f, 0.f, 0.f, 0.f);
        if (gi < total4) CP16(dx, X4 + gi);
        else *(float4*)(smem + RAWX_OFF + p * 8192 + tid * 16) = z;
        if (gi + 256 < total4) CP16(dx + 4096, X4 + gi + 256);
        else *(float4*)(smem + RAWX_OFF + p * 8192 + tid * 16 + 4096) = z;
        if (tid < 64) {
            long long gy = g * 64 + tid;
            if (gy < N) CP16(sb + RAWY_OFF + p * 1024 + tid * 16, Y4 + gy);
            else *(float4*)(smem + RAWY_OFF + p * 1024 + tid * 16) = z;
        }
        CP_COMMIT();
    };

    if (nloc > 0) stage(0);
    if (nloc > 1) stage(1);

    for (int i = 0; i < nloc; i++) {
        const int p = i % 3;
        // committed groups so far: stages 0..min(i+1, nloc-1).
        // Need stage(i) complete: allow 1 outstanding iff stage(i+1) exists.
        if (i + 1 < nloc) { CP_WAIT1(); } else { CP_WAIT0(); }
        __syncthreads();                 // all warps done computing tile i-1
        if (i + 2 < nloc) stage(i + 2);  // buf (i+2)%3 last used at tile i-1

        const float4*     rx  = (const float4*)(smem + RAWX_OFF + p * 8192);
        const ulonglong2* rxu = (const ulonglong2*)rx;
        const float*      sx  = (const float*)rx;
        const ulonglong2* syu = (const ulonglong2*)(smem + RAWY_OFF + p * 1024);

#pragma unroll
        for (int k = 0; k < 8; k++) {
            const int r = w + 8 * k;
            ulonglong2 ia = rxu[r * 8 + 2 * bi];
            ulonglong2 ib = rxu[r * 8 + 2 * bi + 1];
            float4     jv = rx [r * 8 + jq4];
            u64 ap[4] = {ia.x, ia.y, ib.x, ib.y};
            u64 bd[4] = {dup2(jv.x), dup2(jv.y), dup2(jv.z), dup2(jv.w)};
#pragma unroll
            for (int pp = 0; pp < 4; pp++)
#pragma unroll
                for (int q = 0; q < 4; q++) ffma2(acc[pp][q], ap[pp], bd[q]);
        }

#pragma unroll
        for (int k = 0; k < 8; k++) {
            const int r = w + 8 * k;
            float x = sx[r * 32 + l];
            ulonglong2 yp = syu[r];
            u64 xd = dup2(x);
            ffma2(cacc01, xd, yp.x);
            ffma2(cacc23, xd, yp.y);
            add_imm1(sxacc, x);
        }
    }
    __syncthreads();

    {
        float* mg = (float*)(smem + SG_OFF) + w * 1024;
        const int j0 = 8 * bj + 4 * jh;
#pragma unroll
        for (int pp = 0; pp < 4; pp++) {
            const int i0 = 8 * bi + 2 * pp;
#pragma unroll
            for (int q = 0; q < 4; q++) {
                float lo, hi;
                unpack2(acc[pp][q], lo, hi);
                mg[i0 * 32 + j0 + q]       = lo;
                mg[(i0 + 1) * 32 + j0 + q] = hi;
            }
        }
        float* scp = (float*)(smem + SCP_OFF) + w * 128;
        float c0, c1, c2, c3;
        unpack2(cacc01, c0, c1);
        unpack2(cacc23, c2, c3);
        scp[l * 4 + 0] = c0; scp[l * 4 + 1] = c1;
        scp[l * 4 + 2] = c2; scp[l * 4 + 3] = c3;
        ((float*)(smem + SXP_OFF))[w * 32 + l] = sxacc;
    }
    __syncthreads();

    {
        const float* sg = (const float*)(smem + SG_OFF);
        for (int e = tid; e < 1024; e += TPB) {
            float s = 0.f;
#pragma unroll
            for (int ww = 0; ww < 8; ww++) s += sg[ww * 1024 + e];
            atomicAdd(&ACC[e], s);
        }
        if (tid < 128) {
            const float* scp = (const float*)(smem + SCP_OFF);
            float s = 0.f;
#pragma unroll
            for (int ww = 0; ww < 8; ww++) s += scp[ww * 128 + tid];
            atomicAdd(&ACC[1056 + tid], s);
        }
        if (tid < 32) {
            const float* sxp = (const float*)(smem + SXP_OFF);
            float s = 0.f;
#pragma unroll
            for (int ww = 0; ww < 8; ww++) s += sxp[ww * 32 + tid];
            atomicAdd(&ACC[1024 + tid], s);
        }
    }
}

// ---------------------------------------------------------------------------
__global__ __launch_bounds__(256) void solve_kernel(float* __restrict__ out, float Nf)
{
    __shared__ float G[33 * 33];
    __shared__ float c[132];
    __shared__ float Zb[2][132];
    __shared__ float rowsum[33];
    __shared__ float stepSh;
    __shared__ float ysred[4][64];

    const int tid = threadIdx.x;

    {
        const int m = tid & 3, ch = tid >> 2;
        float s = 0.f;
        for (int j = ch; j < NCTA; j += 64) s += YSP[j * 4 + m];
        ysred[m][ch] = s;
    }

    for (int e = tid; e < 1024; e += 256) {
        int i = e >> 5, j = e & 31;
        G[i * 33 + j] = ACC[e];
    }
    if (tid < 32) {
        float s = ACC[1024 + tid];
        G[tid * 33 + 32] = s;
        G[32 * 33 + tid] = s;
    }
    if (tid == 0) G[32 * 33 + 32] = Nf;
    if (tid < 128) c[tid] = ACC[1056 + tid];
    if (tid < 132) Zb[0][tid] = 0.0f;
    __syncthreads();

    if (tid < 4) {
        float s = 0.f;
#pragma unroll
        for (int k = 0; k < 64; k++) s += ysred[tid][k];
        c[128 + tid] = s;
    }
    if (tid < 33) {
        float s = 0.f;
        for (int j = 0; j < 33; j++) s += fabsf(G[tid * 33 + j]);
        rowsum[tid] = s;
    }
    __syncthreads();
    if (tid == 0) {
        float L = 0.f;
        for (int i = 0; i < 33; i++) L = fmaxf(L, rowsum[i]);
        stepSh = 1.0f / L;
    }
    __syncthreads();
    const float step = stepSh;

    const int i = tid >> 2, m = tid & 3;
    int cur = 0;
    for (int it = 0; it < PGD_ITERS; it++) {
        if (tid < 132) {
            const float* Z = Zb[cur];
            float dot = 0.f;
#pragma unroll
            for (int j = 0; j < 33; j++) dot += G[i * 33 + j] * Z[j * 4 + m];
            float zn = Z[tid] - step * (dot - c[tid]);
            if (i < 32) zn = fmaxf(zn, 0.0f);
            Zb[cur ^ 1][tid] = zn;
        }
        __syncthreads();
        cur ^= 1;
    }
    if (tid < 128) out[tid] = Zb[cur][tid];
}

// ---------------------------------------------------------------------------
extern "C" void kernel_launch(void* const* d_in, const int* in_sizes, int n_in,
                              void* d_out, int out_size)
{
    const float* X = (const float*)d_in[0];
    const float* Y = (const float*)d_in[1];
    const int N = in_sizes[0] / 32;
    const int ntiles = (N + TROWS - 1) / TROWS;

    cudaFuncSetAttribute(gram_kernel,
                         cudaFuncAttributeMaxDynamicSharedMemorySize, SMEMSZ);

    init_kernel<<<NCTA, 256>>>(Y, N);
    gram_kernel<<<NCTA, TPB, SMEMSZ>>>(X, Y, ntiles, N);
    solve_kernel<<<1, 256>>>((float*)d_out, (float)N);
}